// round 1
// baseline (speedup 1.0000x reference)
#include <cuda_runtime.h>
#include <math.h>

// Problem constants
#define BB 64
#define LL 512
#define EE 64
#define HH 8
#define DD 8
#define NROWS (BB*LL)             // 32768
#define OUT_ELEMS (BB*LL*EE)      // 2097152

// Scratch (device globals; no allocation allowed)
__device__ float g_qh[NROWS*EE];
__device__ float g_kh[NROWS*EE];
__device__ float g_vh[NROWS*EE];
__device__ float g_ctx[NROWS*EE];

// ---------------------------------------------------------------------------
// Kernel 1: Y[r][o] = (sum_i X[r][i] * W[o][i] + b[o]) * oscale
// Block: 256 threads, 64 rows per block. W tile in shared (stride 68,
// conflict-free float4 reads). Thread computes 1 output col x 4 rows.
// ---------------------------------------------------------------------------
__global__ __launch_bounds__(256) void linear64_kernel(
    const float* __restrict__ X, const float* __restrict__ W,
    const float* __restrict__ bias, float* __restrict__ Y, float oscale)
{
    __shared__ float Ws[64*68];
    __shared__ float bs[64];
    __shared__ float xs[16*68];
    const int t = threadIdx.x;

    for (int idx = t; idx < 1024; idx += 256) {
        int o = idx >> 4, i4 = (idx & 15) << 2;
        *(float4*)&Ws[o*68 + i4] = *(const float4*)&W[o*64 + i4];
    }
    if (t < 64) bs[t] = bias[t];

    const int o = t & 63, rg = t >> 6;
    const int row0 = blockIdx.x * 64;

    for (int s = 0; s < 4; s++) {
        const int rbase = row0 + s*16;
        __syncthreads();
        {
            int rr = t >> 4, i4 = (t & 15) << 2;
            *(float4*)&xs[rr*68 + i4] = *(const float4*)&X[(rbase+rr)*64 + i4];
        }
        __syncthreads();
        float a0 = bs[o], a1 = bs[o], a2 = bs[o], a3 = bs[o];
        #pragma unroll
        for (int i4 = 0; i4 < 64; i4 += 4) {
            float4 w  = *(float4*)&Ws[o*68 + i4];
            float4 x0 = *(float4*)&xs[(rg*4+0)*68 + i4];
            float4 x1 = *(float4*)&xs[(rg*4+1)*68 + i4];
            float4 x2 = *(float4*)&xs[(rg*4+2)*68 + i4];
            float4 x3 = *(float4*)&xs[(rg*4+3)*68 + i4];
            a0 += w.x*x0.x + w.y*x0.y + w.z*x0.z + w.w*x0.w;
            a1 += w.x*x1.x + w.y*x1.y + w.z*x1.z + w.w*x1.w;
            a2 += w.x*x2.x + w.y*x2.y + w.z*x2.z + w.w*x2.w;
            a3 += w.x*x3.x + w.y*x3.y + w.z*x3.z + w.w*x3.w;
        }
        Y[(rbase+rg*4+0)*64 + o] = a0 * oscale;
        Y[(rbase+rg*4+1)*64 + o] = a1 * oscale;
        Y[(rbase+rg*4+2)*64 + o] = a2 * oscale;
        Y[(rbase+rg*4+3)*64 + o] = a3 * oscale;
    }
}

// ---------------------------------------------------------------------------
// Kernel 2: attention. Block = (q-tile of 64, batch). 128 threads:
// thread = (qgroup of 4 queries, head). Pass 1: Z per (q,h) in regs.
// Pass 2: p = exp(s)/Z, ctx accumulation in regs, head-sum via width-8 shfl,
// attn_wts staged in shared and written coalesced.
// ---------------------------------------------------------------------------
__global__ __launch_bounds__(128) void attn_kernel(float* __restrict__ attn_out)
{
    extern __shared__ float sm[];
    float* ks = sm;               // 64*68
    float* vs = sm + 64*68;       // 64*68
    float* aw = sm + 2*64*68;     // 64*68

    const int b  = blockIdx.y;
    const int q0 = blockIdx.x * 64;
    const int t  = threadIdx.x;
    const int qg = t >> 3, h = t & 7;

    // q fragment (scale already folded in by projection kernel)
    float qf[4][8];
    {
        const float* qb = g_qh + (size_t)((b*LL + q0 + qg*4) * EE) + h*8;
        #pragma unroll
        for (int j = 0; j < 4; j++) {
            float4 a0 = *(const float4*)(qb + j*EE);
            float4 a1 = *(const float4*)(qb + j*EE + 4);
            qf[j][0]=a0.x; qf[j][1]=a0.y; qf[j][2]=a0.z; qf[j][3]=a0.w;
            qf[j][4]=a1.x; qf[j][5]=a1.y; qf[j][6]=a1.z; qf[j][7]=a1.w;
        }
    }

    // ---- Pass 1: Z ----
    float Z[4] = {0.f, 0.f, 0.f, 0.f};
    for (int c = 0; c < 8; c++) {
        __syncthreads();
        const float* kb = g_kh + (size_t)((b*LL + c*64) * EE);
        for (int idx = t; idx < 1024; idx += 128) {
            int m = idx >> 4, i4 = (idx & 15) << 2;
            *(float4*)&ks[m*68 + i4] = *(const float4*)(kb + m*EE + i4);
        }
        __syncthreads();
        #pragma unroll 2
        for (int m = 0; m < 64; m++) {
            float4 k0 = *(float4*)&ks[m*68 + h*8];
            float4 k1 = *(float4*)&ks[m*68 + h*8 + 4];
            #pragma unroll
            for (int j = 0; j < 4; j++) {
                float s = qf[j][0]*k0.x + qf[j][1]*k0.y + qf[j][2]*k0.z + qf[j][3]*k0.w
                        + qf[j][4]*k1.x + qf[j][5]*k1.y + qf[j][6]*k1.z + qf[j][7]*k1.w;
                Z[j] += __expf(s);
            }
        }
    }
    float Zi[4];
    #pragma unroll
    for (int j = 0; j < 4; j++) Zi[j] = 1.0f / Z[j];

    // ---- Pass 2: ctx + attn_wts ----
    float cx[4][8];
    #pragma unroll
    for (int j = 0; j < 4; j++)
        #pragma unroll
        for (int d = 0; d < 8; d++) cx[j][d] = 0.f;

    for (int c = 0; c < 8; c++) {
        __syncthreads();
        const float* kb = g_kh + (size_t)((b*LL + c*64) * EE);
        const float* vb = g_vh + (size_t)((b*LL + c*64) * EE);
        for (int idx = t; idx < 1024; idx += 128) {
            int m = idx >> 4, i4 = (idx & 15) << 2;
            *(float4*)&ks[m*68 + i4] = *(const float4*)(kb + m*EE + i4);
            *(float4*)&vs[m*68 + i4] = *(const float4*)(vb + m*EE + i4);
        }
        __syncthreads();
        for (int m = 0; m < 64; m++) {
            float4 k0 = *(float4*)&ks[m*68 + h*8];
            float4 k1 = *(float4*)&ks[m*68 + h*8 + 4];
            float4 v0 = *(float4*)&vs[m*68 + h*8];
            float4 v1 = *(float4*)&vs[m*68 + h*8 + 4];
            float p[4];
            #pragma unroll
            for (int j = 0; j < 4; j++) {
                float s = qf[j][0]*k0.x + qf[j][1]*k0.y + qf[j][2]*k0.z + qf[j][3]*k0.w
                        + qf[j][4]*k1.x + qf[j][5]*k1.y + qf[j][6]*k1.z + qf[j][7]*k1.w;
                p[j] = __expf(s) * Zi[j];
            }
            #pragma unroll
            for (int j = 0; j < 4; j++) {
                cx[j][0] += p[j]*v0.x; cx[j][1] += p[j]*v0.y;
                cx[j][2] += p[j]*v0.z; cx[j][3] += p[j]*v0.w;
                cx[j][4] += p[j]*v1.x; cx[j][5] += p[j]*v1.y;
                cx[j][6] += p[j]*v1.z; cx[j][7] += p[j]*v1.w;
            }
            #pragma unroll
            for (int j = 0; j < 4; j++) {
                float a = p[j];
                a += __shfl_xor_sync(0xffffffffu, a, 1, 8);
                a += __shfl_xor_sync(0xffffffffu, a, 2, 8);
                a += __shfl_xor_sync(0xffffffffu, a, 4, 8);
                if (h == 0) aw[(qg*4+j)*68 + m] = a * 0.125f;
            }
        }
        __syncthreads();
        float* ob = attn_out + ((size_t)(b*LL) + q0) * LL + c*64;
        for (int idx = t; idx < 1024; idx += 128) {
            int qq = idx >> 4, m4 = (idx & 15) << 2;
            *(float4*)(ob + (size_t)qq*LL + m4) = *(float4*)&aw[qq*68 + m4];
        }
    }

    // write ctx
    float* cb = g_ctx + (size_t)((b*LL + q0 + qg*4) * EE) + h*8;
    #pragma unroll
    for (int j = 0; j < 4; j++) {
        *(float4*)(cb + j*EE)     = make_float4(cx[j][0], cx[j][1], cx[j][2], cx[j][3]);
        *(float4*)(cb + j*EE + 4) = make_float4(cx[j][4], cx[j][5], cx[j][6], cx[j][7]);
    }
}

// ---------------------------------------------------------------------------
// Kernel 3: epilogue. O-proj + residual + LN1 + FF1(relu) + FF2 + residual + LN2.
// Block: 256 threads, 64 rows; 3 weight matrices resident in shared.
// ---------------------------------------------------------------------------
__global__ __launch_bounds__(256) void epilogue_kernel(
    const float* __restrict__ prev,
    const float* __restrict__ Wo, const float* __restrict__ bo,
    const float* __restrict__ ln1g, const float* __restrict__ ln1b,
    const float* __restrict__ W1, const float* __restrict__ b1,
    const float* __restrict__ W2, const float* __restrict__ b2,
    const float* __restrict__ ln2g, const float* __restrict__ ln2b,
    float* __restrict__ out)
{
    extern __shared__ float sm[];
    float* WoS = sm;                 // 64*68
    float* W1S = WoS + 64*68;
    float* W2S = W1S + 64*68;
    float* xs  = W2S + 64*68;        // 16*68
    float* ys  = xs + 16*68;         // 16*68
    float* mvS = ys + 16*68;         // 32
    float* prm = mvS + 32;           // 7*64

    const int t = threadIdx.x;
    for (int idx = t; idx < 1024; idx += 256) {
        int o = idx >> 4, i4 = (idx & 15) << 2;
        *(float4*)&WoS[o*68 + i4] = *(const float4*)&Wo[o*64 + i4];
        *(float4*)&W1S[o*68 + i4] = *(const float4*)&W1[o*64 + i4];
        *(float4*)&W2S[o*68 + i4] = *(const float4*)&W2[o*64 + i4];
    }
    if (t < 64) {
        prm[t]       = bo[t];   prm[64 + t]  = b1[t];  prm[128 + t] = b2[t];
        prm[192 + t] = ln1g[t]; prm[256 + t] = ln1b[t];
        prm[320 + t] = ln2g[t]; prm[384 + t] = ln2b[t];
    }

    const int o = t & 63, rg = t >> 6;
    const int row0 = blockIdx.x * 64;
    const int rrS = t >> 4, cS = t & 15;   // stats mapping

    for (int s = 0; s < 4; s++) {
        const int rbase = row0 + s*16;
        __syncthreads();
        {   // stage ctx
            int rr = t >> 4, i4 = (t & 15) << 2;
            *(float4*)&xs[rr*68 + i4] = *(const float4*)&g_ctx[(rbase+rr)*EE + i4];
        }
        __syncthreads();

        // GEMM1: mha = ctx @ Wo^T + bo, + prev
        float acc[4];
        #pragma unroll
        for (int j = 0; j < 4; j++) acc[j] = prm[o];
        #pragma unroll
        for (int i4 = 0; i4 < 64; i4 += 4) {
            float4 w = *(float4*)&WoS[o*68 + i4];
            #pragma unroll
            for (int j = 0; j < 4; j++) {
                float4 x = *(float4*)&xs[(rg*4+j)*68 + i4];
                acc[j] += w.x*x.x + w.y*x.y + w.z*x.z + w.w*x.w;
            }
        }
        #pragma unroll
        for (int j = 0; j < 4; j++) {
            acc[j] += prev[(rbase+rg*4+j)*EE + o];
            ys[(rg*4+j)*68 + o] = acc[j];
        }
        __syncthreads();

        // LN1 stats
        {
            float s1 = 0.f, s2 = 0.f;
            #pragma unroll
            for (int ii = 0; ii < 4; ii++) {
                float v = ys[rrS*68 + cS + ii*16]; s1 += v; s2 += v*v;
            }
            #pragma unroll
            for (int off = 8; off; off >>= 1) {
                s1 += __shfl_xor_sync(0xffffffffu, s1, off, 16);
                s2 += __shfl_xor_sync(0xffffffffu, s2, off, 16);
            }
            if (cS == 0) {
                float mu = s1 * (1.0f/64.0f);
                float var = s2 * (1.0f/64.0f) - mu*mu;
                mvS[rrS*2]     = mu;
                mvS[rrS*2 + 1] = rsqrtf(var + 1e-5f);
            }
        }
        __syncthreads();

        // normalize -> x (keep in regs for residual2, also into xs for GEMM2)
        float xr[4];
        #pragma unroll
        for (int j = 0; j < 4; j++) {
            int rr = rg*4 + j;
            float v = ys[rr*68 + o];
            float xn = (v - mvS[rr*2]) * mvS[rr*2+1] * prm[192 + o] + prm[256 + o];
            xr[j] = xn;
            xs[rr*68 + o] = xn;
        }
        __syncthreads();

        // GEMM2: h1 = relu(x @ W1^T + b1) -> ys
        #pragma unroll
        for (int j = 0; j < 4; j++) acc[j] = prm[64 + o];
        #pragma unroll
        for (int i4 = 0; i4 < 64; i4 += 4) {
            float4 w = *(float4*)&W1S[o*68 + i4];
            #pragma unroll
            for (int j = 0; j < 4; j++) {
                float4 x = *(float4*)&xs[(rg*4+j)*68 + i4];
                acc[j] += w.x*x.x + w.y*x.y + w.z*x.z + w.w*x.w;
            }
        }
        #pragma unroll
        for (int j = 0; j < 4; j++) ys[(rg*4+j)*68 + o] = fmaxf(acc[j], 0.f);
        __syncthreads();

        // GEMM3: f = h1 @ W2^T + b2 + x -> xs (for stats), regs
        #pragma unroll
        for (int j = 0; j < 4; j++) acc[j] = prm[128 + o];
        #pragma unroll
        for (int i4 = 0; i4 < 64; i4 += 4) {
            float4 w = *(float4*)&W2S[o*68 + i4];
            #pragma unroll
            for (int j = 0; j < 4; j++) {
                float4 x = *(float4*)&ys[(rg*4+j)*68 + i4];
                acc[j] += w.x*x.x + w.y*x.y + w.z*x.z + w.w*x.w;
            }
        }
        float fr[4];
        #pragma unroll
        for (int j = 0; j < 4; j++) {
            fr[j] = acc[j] + xr[j];
            xs[(rg*4+j)*68 + o] = fr[j];
        }
        __syncthreads();

        // LN2 stats
        {
            float s1 = 0.f, s2 = 0.f;
            #pragma unroll
            for (int ii = 0; ii < 4; ii++) {
                float v = xs[rrS*68 + cS + ii*16]; s1 += v; s2 += v*v;
            }
            #pragma unroll
            for (int off = 8; off; off >>= 1) {
                s1 += __shfl_xor_sync(0xffffffffu, s1, off, 16);
                s2 += __shfl_xor_sync(0xffffffffu, s2, off, 16);
            }
            if (cS == 0) {
                float mu = s1 * (1.0f/64.0f);
                float var = s2 * (1.0f/64.0f) - mu*mu;
                mvS[rrS*2]     = mu;
                mvS[rrS*2 + 1] = rsqrtf(var + 1e-5f);
            }
        }
        __syncthreads();

        #pragma unroll
        for (int j = 0; j < 4; j++) {
            int rr = rg*4 + j;
            out[(rbase+rr)*EE + o] =
                (fr[j] - mvS[rr*2]) * mvS[rr*2+1] * prm[320 + o] + prm[384 + o];
        }
    }
}

// ---------------------------------------------------------------------------
extern "C" void kernel_launch(void* const* d_in, const int* in_sizes, int n_in,
                              void* d_out, int out_size)
{
    const float* q    = (const float*)d_in[0];
    const float* k    = (const float*)d_in[1];
    const float* prev = (const float*)d_in[2];
    const float* Wq   = (const float*)d_in[3];
    const float* bq   = (const float*)d_in[4];
    const float* Wk   = (const float*)d_in[5];
    const float* bk   = (const float*)d_in[6];
    const float* Wv   = (const float*)d_in[7];
    const float* bv   = (const float*)d_in[8];
    const float* Wo   = (const float*)d_in[9];
    const float* bo   = (const float*)d_in[10];
    const float* ln1g = (const float*)d_in[11];
    const float* ln1b = (const float*)d_in[12];
    const float* W1   = (const float*)d_in[13];
    const float* b1   = (const float*)d_in[14];
    const float* W2   = (const float*)d_in[15];
    const float* b2   = (const float*)d_in[16];
    const float* ln2g = (const float*)d_in[17];
    const float* ln2b = (const float*)d_in[18];

    float* out      = (float*)d_out;
    float* attn_out = out + OUT_ELEMS;

    void* p;
    cudaGetSymbolAddress(&p, g_qh); float* p_qh = (float*)p;
    cudaGetSymbolAddress(&p, g_kh); float* p_kh = (float*)p;
    cudaGetSymbolAddress(&p, g_vh); float* p_vh = (float*)p;

    const int ATTN_SMEM = 3*64*68*4;                       // 52224 B
    const int EPI_SMEM  = (3*64*68 + 2*16*68 + 32 + 7*64)*4; // 62848 B
    cudaFuncSetAttribute(attn_kernel,
        cudaFuncAttributeMaxDynamicSharedMemorySize, ATTN_SMEM);
    cudaFuncSetAttribute(epilogue_kernel,
        cudaFuncAttributeMaxDynamicSharedMemorySize, EPI_SMEM);

    const float qscale = 0.35355339059327373f; // 1/sqrt(8)

    linear64_kernel<<<NROWS/64, 256>>>(q, Wq, bq, p_qh, qscale);
    linear64_kernel<<<NROWS/64, 256>>>(k, Wk, bk, p_kh, 1.0f);
    linear64_kernel<<<NROWS/64, 256>>>(k, Wv, bv, p_vh, 1.0f);

    attn_kernel<<<dim3(LL/64, BB), 128, ATTN_SMEM>>>(attn_out);

    epilogue_kernel<<<NROWS/64, 256, EPI_SMEM>>>(
        prev, Wo, bo, ln1g, ln1b, W1, b1, W2, b2, ln2g, ln2b, out);
}